// round 9
// baseline (speedup 1.0000x reference)
#include <cuda_runtime.h>
#include <math.h>

// HyperbolicMLR fused: class prep + dual GEMM (dot(p,x), dot(a,x)) + mobius/asinh.
// B=2048, C=1000, D=64 fp32. Block 128b x 64c, thread 8b x 4c, FFMA2 with b-pairs.
// Class tiles stored pair-DUPLICATED so the x operand needs no register packing.

#define K_CURV 0.1f
#define SQRT_K 0.31622776601683794f
#define DDIM   64

// dynamic smem layout (bytes)
#define SM_XS   0                      // x tile [d][b ^ (d&60)]        64*128*4 = 32768
#define SM_PS   32768                  // p_poin dup-pairs [d][perm]    64*128*4 = 32768
#define SM_QS   65536                  // a_poin dup-pairs [d][perm]    64*128*4 = 32768
#define SM_X2   98304                  // |p_poin|^2      [64]
#define SM_PA   98560                  // dot(mp,a_poin)  [64]
#define SM_SC   98816                  // scale           [64]
#define SM_CF   99072                  // 2*sqrt_k/a_norm [64]
#define SM_Y2   99328                  // |x_b|^2         [128]
#define SM_TOTAL 99840

// ---- packed f32x2 / approx-MUFU helpers ----
__device__ __forceinline__ unsigned long long pack2(float a, float b) {
    unsigned long long r;
    asm("mov.b64 %0, {%1, %2};" : "=l"(r) : "f"(a), "f"(b));
    return r;
}
__device__ __forceinline__ float2 unpack2(unsigned long long v) {
    float2 r;
    asm("mov.b64 {%0, %1}, %2;" : "=f"(r.x), "=f"(r.y) : "l"(v));
    return r;
}
__device__ __forceinline__ void ffma2(unsigned long long& acc,
                                      unsigned long long a, unsigned long long b) {
    asm("fma.rn.f32x2 %0, %1, %2, %0;" : "+l"(acc) : "l"(a), "l"(b));
}
__device__ __forceinline__ float rcp_a(float x)  { float r; asm("rcp.approx.f32 %0, %1;"  : "=f"(r) : "f"(x)); return r; }
__device__ __forceinline__ float sqrt_a(float x) { float r; asm("sqrt.approx.f32 %0, %1;" : "=f"(r) : "f"(x)); return r; }
__device__ __forceinline__ float lg2_a(float x)  { float r; asm("lg2.approx.f32 %0, %1;"  : "=f"(r) : "f"(x)); return r; }

__global__ void __launch_bounds__(256, 2)
hmlr_fused(const float* __restrict__ x,
           const float* __restrict__ a_vals,
           const float* __restrict__ p_vals,
           float* __restrict__ out, int B, int C) {
    extern __shared__ __align__(16) char smem[];
    float* xs   = (float*)(smem + SM_XS);
    float* ps   = (float*)(smem + SM_PS);
    float* qs   = (float*)(smem + SM_QS);
    float* s_x2 = (float*)(smem + SM_X2);
    float* s_pa = (float*)(smem + SM_PA);
    float* s_sc = (float*)(smem + SM_SC);
    float* s_cf = (float*)(smem + SM_CF);
    float* s_y2 = (float*)(smem + SM_Y2);

    const int tid   = threadIdx.x;
    const int cBase = blockIdx.x * 64;
    const int bBase = blockIdx.y * 128;

    // ================= phase 1a: x tile fill (transpose + swizzle) + y2 ========
    {
        const float4* Xv = (const float4*)(x + (size_t)bBase * DDIM);
#pragma unroll
        for (int it = 0; it < 8; ++it) {
            int lin = tid + it * 256;           // 0..2047 = r*16 + ch
            float4 v = Xv[lin];
            int r  = lin >> 4;                  // b row 0..127
            int ch = lin & 15;                  // d chunk
            int db = ch * 4;                    // d base, multiple of 4
            int pb = r ^ db;                    // swizzled column (db == db&60)
            xs[(db + 0) * 128 + pb] = v.x;
            xs[(db + 1) * 128 + pb] = v.y;
            xs[(db + 2) * 128 + pb] = v.z;
            xs[(db + 3) * 128 + pb] = v.w;
            float s = v.x * v.x + v.y * v.y + v.z * v.z + v.w * v.w;
            s += __shfl_xor_sync(0xffffffffu, s, 8);
            s += __shfl_xor_sync(0xffffffffu, s, 4);
            s += __shfl_xor_sync(0xffffffffu, s, 2);
            s += __shfl_xor_sync(0xffffffffu, s, 1);
            if (ch == 0) s_y2[r] = s;
        }
    }

    // ================= phase 1b: class prep (quad of lanes per class) ==========
    {
        const int cl = tid >> 2;                // local class 0..63
        const int sq = tid & 3;                 // quad lane: d in [sq*16, sq*16+16)
        const int cc = cBase + cl;
        const bool valid = (cc < C);

        float P[16], A[16];
        if (valid) {
            const float4* pb4 = (const float4*)(p_vals + (size_t)cc * DDIM + sq * 16);
            const float4* ab4 = (const float4*)(a_vals + (size_t)cc * DDIM + sq * 16);
#pragma unroll
            for (int i = 0; i < 4; ++i) {
                float4 pv = pb4[i], av = ab4[i];
                P[i*4+0]=pv.x; P[i*4+1]=pv.y; P[i*4+2]=pv.z; P[i*4+3]=pv.w;
                A[i*4+0]=av.x; A[i*4+1]=av.y; A[i*4+2]=av.z; A[i*4+3]=av.w;
            }
        } else {
#pragma unroll
            for (int i = 0; i < 16; ++i) { P[i] = 0.f; A[i] = 0.f; }
        }

        float psq = 0.f;
#pragma unroll
        for (int i = 0; i < 16; ++i) psq += P[i] * P[i];
        psq += __shfl_xor_sync(0xffffffffu, psq, 1);
        psq += __shfl_xor_sync(0xffffffffu, psq, 2);

        float pn  = fmaxf(sqrtf(psq), 1e-15f);
        float arg = SQRT_K * pn;
        float t   = tanhf(arg) / arg;           // exp0 factor
        float p2  = t * t * psq;                // |p_poin|^2
        float fac = 1.f + K_CURV * p2;

        float a2 = 0.f, pad = 0.f;
#pragma unroll
        for (int i = 0; i < 16; ++i) {
            float pp = t * P[i];
            float ap = fac * A[i];
            P[i] = pp; A[i] = ap;
            a2  += ap * ap;
            pad += pp * ap;
        }
        a2  += __shfl_xor_sync(0xffffffffu, a2, 1);
        a2  += __shfl_xor_sync(0xffffffffu, a2, 2);
        pad += __shfl_xor_sync(0xffffffffu, pad, 1);
        pad += __shfl_xor_sync(0xffffffffu, pad, 2);

        if (sq == 0) {
            float an  = fmaxf(sqrtf(a2), 1e-15f);
            float lam = 2.f / (1.f - K_CURV * p2);
            s_x2[cl] = p2;
            s_pa[cl] = -pad;                    // dot(mp, a_poin)
            s_sc[cl] = lam * an / SQRT_K;       // scale
            s_cf[cl] = 2.f * SQRT_K / an;       // folded consts
        }
        // store pair-DUPLICATED, permuted so compute LDS.128 is lane-contiguous:
        // class c -> half h=(c>>1)&1, slot16 t=(c>>2)^((d>>2)&15), byte pos (c&1)*8
        const int hB   = ((cl >> 1) & 1) * 64;  // half offset in floats
        const int tIdx = cl >> 2;
        const int pos2 = (cl & 1) * 2;          // float offset within 16B slot
#pragma unroll
        for (int i = 0; i < 16; ++i) {
            int d   = sq * 16 + i;
            int swz = (d >> 2) & 15;
            int fi  = d * 128 + hB + ((tIdx ^ swz) * 4) + pos2;
            *(unsigned long long*)(ps + fi) = pack2(P[i], P[i]);
            *(unsigned long long*)(qs + fi) = pack2(A[i], A[i]);
        }
    }
    __syncthreads();

    // ================= phase 2: dual GEMM, 8b x 4c, zero-MOV inner loop ========
    const int tx = tid & 15;        // class group: c = 4*tx + j
    const int ty = tid >> 4;        // batch group: b = ty*8 + i
    const int b0 = ty * 8;

    unsigned long long accp[4][4], acca[4][4];   // [j=c][bp=b-pair]
#pragma unroll
    for (int j = 0; j < 4; ++j)
#pragma unroll
        for (int bp = 0; bp < 4; ++bp) { accp[j][bp] = 0ull; acca[j][bp] = 0ull; }

#pragma unroll 16
    for (int d = 0; d < DDIM; ++d) {
        const int m   = d & 60;
        const int swz = (d >> 2) & 15;
        const ulonglong2 xlo = *(const ulonglong2*)(xs + d * 128 + ( b0      ^ m));
        const ulonglong2 xhi = *(const ulonglong2*)(xs + d * 128 + ((b0 + 4) ^ m));
        const ulonglong2 p01 = *(const ulonglong2*)(ps + d * 128 +      (tx ^ swz) * 4);
        const ulonglong2 p23 = *(const ulonglong2*)(ps + d * 128 + 64 + (tx ^ swz) * 4);
        const ulonglong2 a01 = *(const ulonglong2*)(qs + d * 128 +      (tx ^ swz) * 4);
        const ulonglong2 a23 = *(const ulonglong2*)(qs + d * 128 + 64 + (tx ^ swz) * 4);
        unsigned long long xp[4] = { xlo.x, xlo.y, xhi.x, xhi.y };
        unsigned long long pd[4] = { p01.x, p01.y, p23.x, p23.y };
        unsigned long long ad[4] = { a01.x, a01.y, a23.x, a23.y };
#pragma unroll
        for (int j = 0; j < 4; ++j)
#pragma unroll
            for (int bp = 0; bp < 4; ++bp) {
                ffma2(accp[j][bp], xp[bp], pd[j]);
                ffma2(acca[j][bp], xp[bp], ad[j]);
            }
    }

    // ================= phase 3: epilogue (single rcp per output) ================
    const int cg = cBase + tx * 4;
    const bool wr = (cg + 3) < C;               // C % 4 == 0: all-in or all-out
    float x2a[4], paa[4], sca[4], cfa[4], Bf[4], twoBf[4], Bf2[4], kkx2[4];
#pragma unroll
    for (int j = 0; j < 4; ++j) {
        x2a[j]  = s_x2[tx * 4 + j];
        paa[j]  = s_pa[tx * 4 + j];
        sca[j]  = s_sc[tx * 4 + j];
        cfa[j]  = s_cf[tx * 4 + j];
        Bf[j]   = 1.f - K_CURV * x2a[j];
        twoBf[j]= 2.f * Bf[j];
        Bf2[j]  = Bf[j] * Bf[j];
        kkx2[j] = (K_CURV * K_CURV) * x2a[j];
    }

#pragma unroll
    for (int bp = 0; bp < 4; ++bp) {
        float2 P2[4], A2[4];
#pragma unroll
        for (int j = 0; j < 4; ++j) { P2[j] = unpack2(accp[j][bp]); A2[j] = unpack2(acca[j][bp]); }
#pragma unroll
        for (int q = 0; q < 2; ++q) {
            const int i  = bp * 2 + q;
            const float y2 = s_y2[b0 + i];
            float4 r;
            float* rp = (float*)&r;
#pragma unroll
            for (int j = 0; j < 4; ++j) {
                float dotp = q ? P2[j].y : P2[j].x;   // dot(p_poin, x)
                float dota = q ? A2[j].y : A2[j].x;   // dot(a_poin, x)
                float xy   = -dotp;                   // dot(mp, x)
                float base = fmaf(2.f * K_CURV, xy, 1.f);
                float Af   = fmaf(K_CURV, y2, base);          // 1+2kxy+k*y2
                float den  = fmaf(kkx2[j], y2, base);         // 1+2kxy+k^2*x2*y2
                float dotnum = fmaf(Af, paa[j], Bf[j] * dota);
                float num  = fmaf(Af, fmaf(Af, x2a[j], twoBf[j] * xy), Bf2[j] * y2);
                float w    = fmaf(den, den, -K_CURV * num);   // den^2 - k*num > 0
                float ratio = cfa[j] * dotnum * den * rcp_a(w);
                float tt = fabsf(ratio);
                float z  = lg2_a(tt + sqrt_a(fmaf(tt, tt, 1.f))) * 0.69314718056f;
                rp[j] = sca[j] * copysignf(z, ratio);
            }
            if (wr) {
                const int bg = bBase + b0 + i;
                *(float4*)(out + (size_t)bg * C + cg) = r;
            }
        }
    }
}

// ===================== launch ==================================================
extern "C" void kernel_launch(void* const* d_in, const int* in_sizes, int n_in,
                              void* d_out, int out_size) {
    const float* x = (const float*)d_in[0];
    const float* a = (const float*)d_in[1];
    const float* p = (const float*)d_in[2];
    float* out = (float*)d_out;
    const int B = in_sizes[0] / DDIM;   // 2048
    const int C = in_sizes[1] / DDIM;   // 1000

    cudaFuncSetAttribute(hmlr_fused, cudaFuncAttributeMaxDynamicSharedMemorySize, SM_TOTAL);
    dim3 grid((C + 63) / 64, B / 128);  // 16 x 16 = 256 blocks
    hmlr_fused<<<grid, 256, SM_TOTAL>>>(x, a, p, out, B, C);
}